// round 1
// baseline (speedup 1.0000x reference)
#include <cuda_runtime.h>
#include <math.h>

// Problem constants
#define BQ    8
#define CIN   256
#define COUT  256
#define NPTS  8192
#define LQ    (3 * NPTS)      // 24576 columns per (batch) GEMM
#define MTOT  (2 * COUT)      // 512 rows: [W_feat; W_dir]

// Scratch (static device globals -- no runtime allocation)
__device__ float g_p[(size_t)BQ * COUT * LQ];   // 192 MiB
__device__ float g_d[(size_t)BQ * COUT * LQ];   // 192 MiB
__device__ float g_sum[COUT];
__device__ float g_sumsq[COUT];
__device__ float g_bn_a[COUT];   // rstd * gamma
__device__ float g_bn_b[COUT];   // beta - mean * rstd * gamma

// ---------------------------------------------------------------------------
// K1: C[512, 24576] = [W_feat; W_dir] @ X_b   per batch
// 128x128x16 tiling, 256 threads, 8x8 per-thread tile
// ---------------------------------------------------------------------------
__global__ __launch_bounds__(256, 2)
void gemm_kernel(const float* __restrict__ x,
                 const float* __restrict__ Wf,
                 const float* __restrict__ Wd)
{
    __shared__ float As[16][128];   // As[k][m]
    __shared__ float Bs[16][128];   // Bs[k][l]

    const int b  = blockIdx.z;
    const int m0 = blockIdx.y * 128;       // 0,128,256,384
    const int l0 = blockIdx.x * 128;

    // block is entirely inside feat rows or dir rows (128 | 256)
    const float* W    = (m0 < COUT) ? Wf : Wd;
    const int    mrel = (m0 < COUT) ? m0 : (m0 - COUT);
    float* Cbase = ((m0 < COUT) ? g_p : g_d) + ((size_t)b * COUT + mrel) * LQ;

    const float* xb = x + (size_t)b * CIN * LQ;

    const int tid = threadIdx.x;
    const int ty  = tid >> 4;    // 0..15  -> rows ty*8..ty*8+7
    const int tx  = tid & 15;    // 0..15  -> cols tx*8..tx*8+7

    float acc[8][8];
#pragma unroll
    for (int i = 0; i < 8; i++)
#pragma unroll
        for (int j = 0; j < 8; j++) acc[i][j] = 0.f;

    for (int k0 = 0; k0 < CIN; k0 += 16) {
        // ---- load A tile: 128 rows x 16 k, transpose into As[k][m] ----
#pragma unroll
        for (int i = 0; i < 2; i++) {
            int f   = tid * 2 + i;          // 0..511 float4 slots
            int row = f >> 2;               // 0..127
            int c4  = (f & 3) * 4;          // 0,4,8,12
            float4 v = *reinterpret_cast<const float4*>(
                W + (size_t)(mrel + row) * CIN + k0 + c4);
            As[c4 + 0][row] = v.x;
            As[c4 + 1][row] = v.y;
            As[c4 + 2][row] = v.z;
            As[c4 + 3][row] = v.w;
        }
        // ---- load B tile: 16 k x 128 l ----
#pragma unroll
        for (int i = 0; i < 2; i++) {
            int f   = tid + i * 256;        // 0..511 float4 slots
            int row = f >> 5;               // 0..15
            int col = (f & 31) * 4;         // 0..124
            float4 v = *reinterpret_cast<const float4*>(
                xb + (size_t)(k0 + row) * LQ + l0 + col);
            *reinterpret_cast<float4*>(&Bs[row][col]) = v;
        }
        __syncthreads();

#pragma unroll
        for (int k = 0; k < 16; k++) {
            float a[8], bb[8];
            *reinterpret_cast<float4*>(&a[0])  = *reinterpret_cast<const float4*>(&As[k][ty * 8]);
            *reinterpret_cast<float4*>(&a[4])  = *reinterpret_cast<const float4*>(&As[k][ty * 8 + 4]);
            *reinterpret_cast<float4*>(&bb[0]) = *reinterpret_cast<const float4*>(&Bs[k][tx * 8]);
            *reinterpret_cast<float4*>(&bb[4]) = *reinterpret_cast<const float4*>(&Bs[k][tx * 8 + 4]);
#pragma unroll
            for (int i = 0; i < 8; i++)
#pragma unroll
                for (int j = 0; j < 8; j++)
                    acc[i][j] = fmaf(a[i], bb[j], acc[i][j]);
        }
        __syncthreads();
    }

    // ---- epilogue: write C tile ----
#pragma unroll
    for (int i = 0; i < 8; i++) {
        float* out = Cbase + (size_t)(ty * 8 + i) * LQ + l0 + tx * 8;
#pragma unroll
        for (int j = 0; j < 8; j += 4) {
            float4 v = make_float4(acc[i][j], acc[i][j + 1], acc[i][j + 2], acc[i][j + 3]);
            *reinterpret_cast<float4*>(out + j) = v;
        }
    }
}

// ---------------------------------------------------------------------------
// K0: zero stats accumulators
// ---------------------------------------------------------------------------
__global__ void zero_stats_kernel()
{
    int i = threadIdx.x;
    g_sum[i]   = 0.f;
    g_sumsq[i] = 0.f;
}

// ---------------------------------------------------------------------------
// K2: per-channel sum / sumsq of vector norms
// grid: (COUT, BQ); block: 256
// ---------------------------------------------------------------------------
__global__ __launch_bounds__(256)
void stats_kernel()
{
    const int o = blockIdx.x;
    const int b = blockIdx.y;
    const float* base = g_p + ((size_t)b * COUT + o) * LQ;

    float s = 0.f, s2 = 0.f;
    for (int n = threadIdx.x; n < NPTS; n += 256) {
        float px = base[n];
        float py = base[NPTS + n];
        float pz = base[2 * NPTS + n];
        float nrm = sqrtf(px * px + py * py + pz * pz);
        s  += nrm;
        s2 += nrm * nrm;
    }
    // block reduce
#pragma unroll
    for (int off = 16; off > 0; off >>= 1) {
        s  += __shfl_down_sync(0xffffffffu, s,  off);
        s2 += __shfl_down_sync(0xffffffffu, s2, off);
    }
    __shared__ float shs[8], shs2[8];
    int wid = threadIdx.x >> 5;
    int lid = threadIdx.x & 31;
    if (lid == 0) { shs[wid] = s; shs2[wid] = s2; }
    __syncthreads();
    if (threadIdx.x == 0) {
        float ts = 0.f, ts2 = 0.f;
#pragma unroll
        for (int w = 0; w < 8; w++) { ts += shs[w]; ts2 += shs2[w]; }
        atomicAdd(&g_sum[o],   ts);
        atomicAdd(&g_sumsq[o], ts2);
    }
}

// ---------------------------------------------------------------------------
// K3: finalize BN affine per channel
// ---------------------------------------------------------------------------
__global__ void finalize_kernel(const float* __restrict__ gamma,
                                const float* __restrict__ beta)
{
    int o = threadIdx.x;
    const float inv = 1.0f / (float)(BQ * NPTS);
    float mean = g_sum[o] * inv;
    float var  = g_sumsq[o] * inv - mean * mean;   // biased, as torch BN / jnp.var
    float rstd = rsqrtf(var + 1e-5f);
    float a = rstd * gamma[o];
    g_bn_a[o] = a;
    g_bn_b[o] = beta[o] - mean * a;
}

// ---------------------------------------------------------------------------
// K4: BN rescale + VN LeakyReLU, fused elementwise
// grid: (NPTS/256, COUT, BQ)
// ---------------------------------------------------------------------------
__global__ __launch_bounds__(256)
void epilogue_kernel(float* __restrict__ out)
{
    const int n = blockIdx.x * 256 + threadIdx.x;
    const int o = blockIdx.y;
    const int b = blockIdx.z;
    const size_t base = ((size_t)b * COUT + o) * LQ + n;

    float px = g_p[base];
    float py = g_p[base + NPTS];
    float pz = g_p[base + 2 * NPTS];
    float dx = g_d[base];
    float dy = g_d[base + NPTS];
    float dz = g_d[base + 2 * NPTS];

    float nrm = sqrtf(px * px + py * py + pz * pz);
    // norm_bn / norm = a + b/norm
    float f = __ldg(&g_bn_a[o]) + __ldg(&g_bn_b[o]) / nrm;
    px *= f; py *= f; pz *= f;

    float dot = px * dx + py * dy + pz * dz;
    float dsq = dx * dx + dy * dy + dz * dz;
    if (dot < 0.f) {
        float c = 0.8f * dot / (dsq + 1e-6f);   // (1 - NEG_SLOPE) = 0.8
        px -= c * dx; py -= c * dy; pz -= c * dz;
    }
    out[base]            = px;
    out[base + NPTS]     = py;
    out[base + 2 * NPTS] = pz;
}

// ---------------------------------------------------------------------------
extern "C" void kernel_launch(void* const* d_in, const int* in_sizes, int n_in,
                              void* d_out, int out_size)
{
    const float* x     = (const float*)d_in[0];
    const float* Wf    = (const float*)d_in[1];
    const float* Wd    = (const float*)d_in[2];
    const float* gamma = (const float*)d_in[3];
    const float* beta  = (const float*)d_in[4];
    float* out = (float*)d_out;

    dim3 gemm_grid(LQ / 128, MTOT / 128, BQ);   // (192, 4, 8)
    gemm_kernel<<<gemm_grid, 256>>>(x, Wf, Wd);

    zero_stats_kernel<<<1, COUT>>>();

    dim3 stats_grid(COUT, BQ);
    stats_kernel<<<stats_grid, 256>>>();

    finalize_kernel<<<1, COUT>>>(gamma, beta);

    dim3 epi_grid(NPTS / 256, COUT, BQ);
    epilogue_kernel<<<epi_grid, 256>>>(out);
}